// round 2
// baseline (speedup 1.0000x reference)
#include <cuda_runtime.h>
#include <cuda_bf16.h>
#include <cstdint>

// out[i,j,e] = W[e, pos] + b[e],  pos = clip(idxs[j]-idxs[i], -32, 32) + 32
// Table T[pos][e] (65 x 128 fp32 = 33 KB) built per-block in shared, then
// pure streaming float4 stores of the 512 MB output.

#define MAX_GAP 32
#define NPOS    (2 * MAX_GAP + 1)   // 65
#define EDIM    128
#define E4      (EDIM / 4)          // 32 float4 per vector
#define SMAX    1024

__global__ __launch_bounds__(256, 4)
void rpe2d_kernel(const int* __restrict__ idxs,
                  const float* __restrict__ W,   // (E, NPOS) row-major
                  const float* __restrict__ b,   // (E,)
                  float4* __restrict__ out,      // (S, S, E) as float4 rows
                  int S)
{
    __shared__ float4 T[NPOS * E4];       // T[p*32 + e4]
    __shared__ unsigned char pos_s[SMAX]; // per-column relative position

    const int tid = threadIdx.x;
    const int i   = blockIdx.x;

    // Build lookup table: T[p][e4] = { W[e+k][p] + b[e+k] }
    for (int t = tid; t < NPOS * E4; t += blockDim.x) {
        const int p  = t >> 5;        // 0..64
        const int e4 = t & 31;        // 0..31
        const int e  = e4 * 4;
        float4 v;
        v.x = W[(e + 0) * NPOS + p] + b[e + 0];
        v.y = W[(e + 1) * NPOS + p] + b[e + 1];
        v.z = W[(e + 2) * NPOS + p] + b[e + 2];
        v.w = W[(e + 3) * NPOS + p] + b[e + 3];
        T[t] = v;
    }

    // Per-column positions for this row i
    const int base = idxs[i];
    for (int j = tid; j < S; j += blockDim.x) {
        int d = idxs[j] - base;
        d = min(max(d, -MAX_GAP), MAX_GAP) + MAX_GAP;
        pos_s[j] = (unsigned char)d;
    }
    __syncthreads();

    // Streaming stores: row i is S*E floats = S*32 float4.
    // __stcs: evict-first / streaming hint — output is write-once.
    float4* __restrict__ row = out + (size_t)i * S * E4;
    const int total = S * E4;
    #pragma unroll 4
    for (int f = tid; f < total; f += blockDim.x) {
        const int j  = f >> 5;
        const int e4 = f & 31;
        __stcs(&row[f], T[(int)pos_s[j] * E4 + e4]);
    }
}

extern "C" void kernel_launch(void* const* d_in, const int* in_sizes, int n_in,
                              void* d_out, int out_size) {
    const int*   idxs = (const int*)d_in[0];   // (B*S,) int32
    const float* W    = (const float*)d_in[1]; // (E, NPOS) fp32
    const float* b    = (const float*)d_in[2]; // (E,) fp32
    float4* out = (float4*)d_out;

    const int S = in_sizes[0];                 // B = 1
    rpe2d_kernel<<<S, 256>>>(idxs, W, b, out, S);
}